// round 10
// baseline (speedup 1.0000x reference)
#include <cuda_runtime.h>
#include <cuda_fp16.h>
#include <cuda_bf16.h>
#include <cstdint>

// Problem constants (match reference setup_inputs)
#define NN     50000          // nodes
#define NE     1600000        // edges
#define DIN    256
#define DOUT   256
#define NB     4              // batch
#define MTOT   (NB * NN)      // 200000 rows for the flattened GEMM

// ---------------- device scratch (no allocations allowed) ----------------
// Support stored node-major interleaved: [node][batch][DOUT] fp16
__device__ __half  g_support_h[(size_t)NN * NB * DOUT];  // 102.4 MB
__device__ int     g_deg[NN];
__device__ unsigned long long g_state[128];   // decoupled-lookback {flag,agg}
__device__ int     g_rowptr[NN + 1];
__device__ int     g_wptr[NN];
__device__ int2    g_csr[NE];          // {col, val-as-int} packed per edge

// ---------------- CSR build ----------------
__global__ void zero_kernel() {
    int j = blockIdx.x * blockDim.x + threadIdx.x;
    if (j < NN) g_deg[j] = 0;
    if (j < 128) g_state[j] = 0ULL;
}

__global__ void hist_kernel(const int* __restrict__ rows) {
    int e = blockIdx.x * blockDim.x + threadIdx.x;
    if (e < NE) atomicAdd(&g_deg[rows[e]], 1);
}

// Single-pass exclusive scan with decoupled lookback (98 blocks <= 148 SMs)
#define SCAN_B 512
__global__ void scan_onepass_kernel() {
    __shared__ int sh[SCAN_B];
    __shared__ unsigned s_prefix;
    const int tid = threadIdx.x;
    const int blk = blockIdx.x;
    const int j = blk * SCAN_B + tid;

    int v = (j < NN) ? g_deg[j] : 0;
    sh[tid] = v;
    __syncthreads();
    #pragma unroll
    for (int off = 1; off < SCAN_B; off <<= 1) {
        int t = (tid >= off) ? sh[tid - off] : 0;
        __syncthreads();
        sh[tid] += t;
        __syncthreads();
    }

    // publish block aggregate (flag=1 packed in high word)
    if (tid == SCAN_B - 1)
        atomicExch(&g_state[blk], (1ULL << 32) | (unsigned)sh[SCAN_B - 1]);

    // warp 0: sum aggregates of all predecessor blocks (warp-parallel lookback)
    if (tid < 32) {
        unsigned sum = 0;
        for (int base = blk - 1; base >= 0; base -= 32) {
            int p = base - tid;
            if (p >= 0) {
                unsigned long long st;
                do { st = atomicAdd(&g_state[p], 0ULL); } while ((st >> 32) == 0ULL);
                sum += (unsigned)st;
            }
        }
        sum = __reduce_add_sync(0xffffffffu, sum);
        if (tid == 0) s_prefix = sum;
    }
    __syncthreads();

    if (j < NN) {
        int rp = (int)s_prefix + sh[tid] - v;   // exclusive prefix
        g_rowptr[j] = rp;
        g_wptr[j]   = rp;
    }
    if (blk == 0 && tid == 0) g_rowptr[NN] = NE;
}

__global__ void scatter_kernel(const int* __restrict__ rows,
                               const int* __restrict__ cols,
                               const float* __restrict__ vals) {
    int e = blockIdx.x * blockDim.x + threadIdx.x;
    if (e < NE) {
        int r = rows[e];
        int p = atomicAdd(&g_wptr[r], 1);
        g_csr[p] = make_int2(cols[e], __float_as_int(vals[e]));
    }
}

// ---------------- GEMM: support = X @ W via fp16 tensor cores ----------------
// Block tile 128x128, 8 warps (2 m x 4 n), warp tile 64x32, BK=8,
// double-buffered fp16 smem, mma.sync.m16n8k8.f32.f16.f16.f32.
// Epilogue writes node-major interleaved fp16 support.
#define GBM 128
#define GBN 128
#define GBK 8
#define BSTR 136   // Bs padded col stride (halfs)

__device__ __forceinline__ void mma_f16(float* c, const uint32_t* a, uint32_t b) {
    asm volatile(
        "mma.sync.aligned.m16n8k8.row.col.f32.f16.f16.f32 "
        "{%0,%1,%2,%3}, {%4,%5}, {%6}, {%0,%1,%2,%3};"
        : "+f"(c[0]), "+f"(c[1]), "+f"(c[2]), "+f"(c[3])
        : "r"(a[0]), "r"(a[1]), "r"(b));
}

__global__ __launch_bounds__(256, 2)
void gemm_tc_kernel(const float* __restrict__ A, const float* __restrict__ W) {
    // A: row-major, k contiguous (natural half2 fragment loads)
    __shared__ __half As[2][GBM][GBK];
    // B: k-major, col contiguous, padded stride (conflict-free frag loads)
    __shared__ __half Bs[2][GBK][BSTR];

    const int bx  = blockIdx.x;            // 0..1
    const int by  = blockIdx.y;            // 0..1562
    const int tid = threadIdx.x;
    const int warp = tid >> 5;
    const int lane = tid & 31;
    const int wm = (warp & 1) * 64;        // warp m offset in tile
    const int wn = (warp >> 1) * 32;       // warp n offset in tile
    const int grp = lane >> 2;             // 0..7
    const int tq  = lane & 3;              // 0..3

    // global->smem mappings
    const int aRow = tid >> 1;             // 0..127
    const int aK4  = (tid & 1) * 4;        // 0 or 4
    const int bK   = tid >> 5;             // 0..7
    const int bC4  = (tid & 31) * 4;       // 0..124

    const int gRow = by * GBM + aRow;
    const bool aOk = (gRow < MTOT);
    const float* aPtr = A + (size_t)(aOk ? gRow : 0) * DIN;

    float c[4][4][4];
    #pragma unroll
    for (int i = 0; i < 4; i++)
        #pragma unroll
        for (int j = 0; j < 4; j++)
            #pragma unroll
            for (int r = 0; r < 4; r++) c[i][j][r] = 0.f;

    // prefetch chunk 0
    float4 av = make_float4(0.f, 0.f, 0.f, 0.f);
    if (aOk) av = *(const float4*)(aPtr + aK4);
    float4 bv = *(const float4*)(W + (size_t)bK * DOUT + bx * GBN + bC4);

    const int NCHUNK = DIN / GBK;   // 32
    for (int chunk = 0; chunk < NCHUNK; chunk++) {
        const int buf = chunk & 1;

        {
            __half2 a01 = __floats2half2_rn(av.x, av.y);
            __half2 a23 = __floats2half2_rn(av.z, av.w);
            *(uint2*)&As[buf][aRow][aK4] =
                make_uint2(*(uint32_t*)&a01, *(uint32_t*)&a23);
            __half2 b01 = __floats2half2_rn(bv.x, bv.y);
            __half2 b23 = __floats2half2_rn(bv.z, bv.w);
            *(uint2*)&Bs[buf][bK][bC4] =
                make_uint2(*(uint32_t*)&b01, *(uint32_t*)&b23);
        }
        __syncthreads();

        if (chunk + 1 < NCHUNK) {
            const int kn = (chunk + 1) * GBK;
            if (aOk) av = *(const float4*)(aPtr + kn + aK4);
            bv = *(const float4*)(W + (size_t)(kn + bK) * DOUT + bx * GBN + bC4);
        }

        // B fragments: b = half2(B[2tq][col], B[2tq+1][col])
        uint32_t bfrag[4];
        #pragma unroll
        for (int j = 0; j < 4; j++) {
            const int col = wn + j * 8 + grp;
            __half blo = Bs[buf][tq * 2][col];
            __half bhi = Bs[buf][tq * 2 + 1][col];
            __half2 bb = __halves2half2(blo, bhi);
            bfrag[j] = *(uint32_t*)&bb;
        }

        // A fragments: natural half2 loads (k contiguous)
        uint32_t afrag[4][2];
        #pragma unroll
        for (int i = 0; i < 4; i++) {
            const int r = wm + i * 16 + grp;
            afrag[i][0] = *(const uint32_t*)&As[buf][r][tq * 2];
            afrag[i][1] = *(const uint32_t*)&As[buf][r + 8][tq * 2];
        }

        #pragma unroll
        for (int i = 0; i < 4; i++)
            #pragma unroll
            for (int j = 0; j < 4; j++)
                mma_f16(c[i][j], afrag[i], bfrag[j]);
    }

    // epilogue -> fp16 node-major interleaved: flat row = b*NN + n,
    // dst row = n*NB + b. 16-row groups never straddle batches (50000 % 16 == 0).
    #pragma unroll
    for (int i = 0; i < 4; i++) {
        const int row0 = by * GBM + wm + i * 16 + grp;
        if (row0 < MTOT) {
            const int b0 = row0 / NN;
            const int n0 = row0 - b0 * NN;
            __half* d0 = g_support_h + ((size_t)n0 * NB + b0) * DOUT;
            __half* d1 = g_support_h + ((size_t)(n0 + 8) * NB + b0) * DOUT;
            #pragma unroll
            for (int j = 0; j < 4; j++) {
                const int col = bx * GBN + wn + j * 8 + tq * 2;
                __half2 h01 = __floats2half2_rn(c[i][j][0], c[i][j][1]);
                __half2 h23 = __floats2half2_rn(c[i][j][2], c[i][j][3]);
                *(__half2*)(d0 + col) = h01;
                *(__half2*)(d1 + col) = h23;
            }
        }
    }
}

// ---------------- SpMM: one warp per row, ALL 4 batches, fp16 gather ----------------
__device__ __forceinline__ void fma_half8(float* acc, uint4 x, float v) {
    float2 f0 = __half22float2(*(__half2*)&x.x);
    float2 f1 = __half22float2(*(__half2*)&x.y);
    float2 f2 = __half22float2(*(__half2*)&x.z);
    float2 f3 = __half22float2(*(__half2*)&x.w);
    acc[0] = fmaf(v, f0.x, acc[0]); acc[1] = fmaf(v, f0.y, acc[1]);
    acc[2] = fmaf(v, f1.x, acc[2]); acc[3] = fmaf(v, f1.y, acc[3]);
    acc[4] = fmaf(v, f2.x, acc[4]); acc[5] = fmaf(v, f2.y, acc[5]);
    acc[6] = fmaf(v, f3.x, acc[6]); acc[7] = fmaf(v, f3.y, acc[7]);
}

__global__ __launch_bounds__(256)
void spmm_kernel(const float* __restrict__ bias, float* __restrict__ out) {
    const int warp = threadIdx.x >> 5;
    const int lane = threadIdx.x & 31;
    const int row  = blockIdx.x * 8 + warp;   // 6250 * 8 == 50000 exactly

    const int s = g_rowptr[row];
    const int e = g_rowptr[row + 1];

    float acc[NB][8];
    #pragma unroll
    for (int b = 0; b < NB; b++)
        #pragma unroll
        for (int q = 0; q < 8; q++) acc[b][q] = 0.f;

    int i = s;
    // unroll-by-2 edges x 4 batches: 8 outstanding LDG.128 per lane,
    // each edge gathers one contiguous 2KB region (node-major interleave).
    for (; i + 1 < e; i += 2) {
        int2 ev0 = g_csr[i];
        int2 ev1 = g_csr[i + 1];
        const uint4* p0 = (const uint4*)(g_support_h + (size_t)ev0.x * (NB * DOUT)) + lane;
        const uint4* p1 = (const uint4*)(g_support_h + (size_t)ev1.x * (NB * DOUT)) + lane;
        uint4 x0[NB], x1[NB];
        #pragma unroll
        for (int b = 0; b < NB; b++) x0[b] = p0[b * (DOUT / 8)];
        #pragma unroll
        for (int b = 0; b < NB; b++) x1[b] = p1[b * (DOUT / 8)];
        float v0 = __int_as_float(ev0.y);
        float v1 = __int_as_float(ev1.y);
        #pragma unroll
        for (int b = 0; b < NB; b++) fma_half8(acc[b], x0[b], v0);
        #pragma unroll
        for (int b = 0; b < NB; b++) fma_half8(acc[b], x1[b], v1);
    }
    if (i < e) {
        int2 ev = g_csr[i];
        const uint4* p = (const uint4*)(g_support_h + (size_t)ev.x * (NB * DOUT)) + lane;
        float v = __int_as_float(ev.y);
        #pragma unroll
        for (int b = 0; b < NB; b++) {
            uint4 x = p[b * (DOUT / 8)];
            fma_half8(acc[b], x, v);
        }
    }

    const float4* b4 = (const float4*)(bias + lane * 8);
    float4 bb0 = b4[0], bb1 = b4[1];

    #pragma unroll
    for (int b = 0; b < NB; b++) {
        float4 o0 = make_float4(acc[b][0] + bb0.x, acc[b][1] + bb0.y,
                                acc[b][2] + bb0.z, acc[b][3] + bb0.w);
        float4 o1 = make_float4(acc[b][4] + bb1.x, acc[b][5] + bb1.y,
                                acc[b][6] + bb1.z, acc[b][7] + bb1.w);
        float* o = out + ((size_t)b * NN + row) * DOUT + lane * 8;
        *(float4*)(o)     = o0;
        *(float4*)(o + 4) = o1;
    }
}

// ---------------- launch ----------------
extern "C" void kernel_launch(void* const* d_in, const int* in_sizes, int n_in,
                              void* d_out, int out_size) {
    const float* X    = (const float*)d_in[0];   // [4, 50000, 256]
    const int*   rows = (const int*)  d_in[1];   // [1.6M]
    const int*   cols = (const int*)  d_in[2];   // [1.6M]
    const float* vals = (const float*)d_in[3];   // [1.6M]
    const float* W    = (const float*)d_in[4];   // [256, 256]
    const float* bias = (const float*)d_in[5];   // [256]
    float* out = (float*)d_out;

    const int nScanBlk = (NN + SCAN_B - 1) / SCAN_B;   // 98 (<=148 SMs: lookback safe)

    // CSR build (4 kernels)
    zero_kernel<<<(NN + 255) / 256, 256>>>();
    hist_kernel<<<(NE + 255) / 256, 256>>>(rows);
    scan_onepass_kernel<<<nScanBlk, SCAN_B>>>();
    scatter_kernel<<<(NE + 255) / 256, 256>>>(rows, cols, vals);

    // Dense projection on fp16 tensor cores, interleaved fp16 output
    dim3 ggrid(DOUT / GBN, (MTOT + GBM - 1) / GBM);   // (2, 1563)
    gemm_tc_kernel<<<ggrid, 256>>>(X, W);

    // SpMM + bias: warp per row, all 4 batches per edge (2KB contiguous gather)
    spmm_kernel<<<NN / 8, 256>>>(bias, out);
}

// round 12
// speedup vs baseline: 1.1614x; 1.1614x over previous
#include <cuda_runtime.h>
#include <cuda_fp16.h>
#include <cuda_bf16.h>
#include <cstdint>

// Problem constants (match reference setup_inputs)
#define NN     50000          // nodes
#define NE     1600000        // edges
#define DIN    256
#define DOUT   256
#define NB     4              // batch
#define MTOT   (NB * NN)      // 200000 rows for the flattened GEMM

// ---------------- device scratch (no allocations allowed) ----------------
// Support stored batch-major: [batch][node][DOUT] fp16 (R7 layout — proven fastest)
__device__ __half  g_support_h[(size_t)NB * NN * DOUT];  // 102.4 MB
__device__ int     g_deg[NN];
__device__ unsigned long long g_state[128];   // decoupled-lookback {flag,agg}
__device__ int     g_rowptr[NN + 1];
__device__ int     g_wptr[NN];
__device__ int2    g_csr[NE];          // {col, val-as-int} packed per edge

// ---------------- CSR build ----------------
__global__ void zero_kernel() {
    int j = blockIdx.x * blockDim.x + threadIdx.x;
    if (j < NN) g_deg[j] = 0;
    if (j < 128) g_state[j] = 0ULL;
}

__global__ void hist_kernel(const int* __restrict__ rows) {
    int e = blockIdx.x * blockDim.x + threadIdx.x;
    if (e < NE) atomicAdd(&g_deg[rows[e]], 1);
}

// Single-pass exclusive scan with decoupled lookback (98 blocks <= 148 SMs)
#define SCAN_B 512
__global__ void scan_onepass_kernel() {
    __shared__ int sh[SCAN_B];
    __shared__ unsigned s_prefix;
    const int tid = threadIdx.x;
    const int blk = blockIdx.x;
    const int j = blk * SCAN_B + tid;

    int v = (j < NN) ? g_deg[j] : 0;
    sh[tid] = v;
    __syncthreads();
    #pragma unroll
    for (int off = 1; off < SCAN_B; off <<= 1) {
        int t = (tid >= off) ? sh[tid - off] : 0;
        __syncthreads();
        sh[tid] += t;
        __syncthreads();
    }

    // publish block aggregate (flag=1 packed in high word)
    if (tid == SCAN_B - 1)
        atomicExch(&g_state[blk], (1ULL << 32) | (unsigned)sh[SCAN_B - 1]);

    // warp 0: sum aggregates of all predecessor blocks (warp-parallel lookback)
    if (tid < 32) {
        unsigned sum = 0;
        for (int base = blk - 1; base >= 0; base -= 32) {
            int p = base - tid;
            if (p >= 0) {
                unsigned long long st;
                do { st = atomicAdd(&g_state[p], 0ULL); } while ((st >> 32) == 0ULL);
                sum += (unsigned)st;
            }
        }
        sum = __reduce_add_sync(0xffffffffu, sum);
        if (tid == 0) s_prefix = sum;
    }
    __syncthreads();

    if (j < NN) {
        int rp = (int)s_prefix + sh[tid] - v;   // exclusive prefix
        g_rowptr[j] = rp;
        g_wptr[j]   = rp;
    }
    if (blk == 0 && tid == 0) g_rowptr[NN] = NE;
}

__global__ void scatter_kernel(const int* __restrict__ rows,
                               const int* __restrict__ cols,
                               const float* __restrict__ vals) {
    int e = blockIdx.x * blockDim.x + threadIdx.x;
    if (e < NE) {
        int r = rows[e];
        int p = atomicAdd(&g_wptr[r], 1);
        g_csr[p] = make_int2(cols[e], __float_as_int(vals[e]));
    }
}

// ---------------- GEMM: support = X @ W via fp16 tensor cores ----------------
// Block tile 128x128, 8 warps (2 m x 4 n), warp tile 64x32, BK=8,
// double-buffered fp16 smem, mma.sync.m16n8k8.f32.f16.f16.f32.
#define GBM 128
#define GBN 128
#define GBK 8
#define BSTR 136   // Bs padded col stride (halfs)

__device__ __forceinline__ void mma_f16(float* c, const uint32_t* a, uint32_t b) {
    asm volatile(
        "mma.sync.aligned.m16n8k8.row.col.f32.f16.f16.f32 "
        "{%0,%1,%2,%3}, {%4,%5}, {%6}, {%0,%1,%2,%3};"
        : "+f"(c[0]), "+f"(c[1]), "+f"(c[2]), "+f"(c[3])
        : "r"(a[0]), "r"(a[1]), "r"(b));
}

__global__ __launch_bounds__(256, 2)
void gemm_tc_kernel(const float* __restrict__ A, const float* __restrict__ W) {
    // A: row-major, k contiguous (natural half2 fragment loads)
    __shared__ __half As[2][GBM][GBK];
    // B: k-major, col contiguous, padded stride (conflict-free frag loads)
    __shared__ __half Bs[2][GBK][BSTR];

    const int bx  = blockIdx.x;            // 0..1
    const int by  = blockIdx.y;            // 0..1562
    const int tid = threadIdx.x;
    const int warp = tid >> 5;
    const int lane = tid & 31;
    const int wm = (warp & 1) * 64;        // warp m offset in tile
    const int wn = (warp >> 1) * 32;       // warp n offset in tile
    const int grp = lane >> 2;             // 0..7
    const int tq  = lane & 3;              // 0..3

    // global->smem mappings
    const int aRow = tid >> 1;             // 0..127
    const int aK4  = (tid & 1) * 4;        // 0 or 4
    const int bK   = tid >> 5;             // 0..7
    const int bC4  = (tid & 31) * 4;       // 0..124

    const int gRow = by * GBM + aRow;
    const bool aOk = (gRow < MTOT);
    const float* aPtr = A + (size_t)(aOk ? gRow : 0) * DIN;

    float c[4][4][4];
    #pragma unroll
    for (int i = 0; i < 4; i++)
        #pragma unroll
        for (int j = 0; j < 4; j++)
            #pragma unroll
            for (int r = 0; r < 4; r++) c[i][j][r] = 0.f;

    // prefetch chunk 0
    float4 av = make_float4(0.f, 0.f, 0.f, 0.f);
    if (aOk) av = *(const float4*)(aPtr + aK4);
    float4 bv = *(const float4*)(W + (size_t)bK * DOUT + bx * GBN + bC4);

    const int NCHUNK = DIN / GBK;   // 32
    for (int chunk = 0; chunk < NCHUNK; chunk++) {
        const int buf = chunk & 1;

        {
            __half2 a01 = __floats2half2_rn(av.x, av.y);
            __half2 a23 = __floats2half2_rn(av.z, av.w);
            *(uint2*)&As[buf][aRow][aK4] =
                make_uint2(*(uint32_t*)&a01, *(uint32_t*)&a23);
            __half2 b01 = __floats2half2_rn(bv.x, bv.y);
            __half2 b23 = __floats2half2_rn(bv.z, bv.w);
            *(uint2*)&Bs[buf][bK][bC4] =
                make_uint2(*(uint32_t*)&b01, *(uint32_t*)&b23);
        }
        __syncthreads();

        if (chunk + 1 < NCHUNK) {
            const int kn = (chunk + 1) * GBK;
            if (aOk) av = *(const float4*)(aPtr + kn + aK4);
            bv = *(const float4*)(W + (size_t)(kn + bK) * DOUT + bx * GBN + bC4);
        }

        // B fragments: b = half2(B[2tq][col], B[2tq+1][col])
        uint32_t bfrag[4];
        #pragma unroll
        for (int j = 0; j < 4; j++) {
            const int col = wn + j * 8 + grp;
            __half blo = Bs[buf][tq * 2][col];
            __half bhi = Bs[buf][tq * 2 + 1][col];
            __half2 bb = __halves2half2(blo, bhi);
            bfrag[j] = *(uint32_t*)&bb;
        }

        // A fragments: natural half2 loads (k contiguous)
        uint32_t afrag[4][2];
        #pragma unroll
        for (int i = 0; i < 4; i++) {
            const int r = wm + i * 16 + grp;
            afrag[i][0] = *(const uint32_t*)&As[buf][r][tq * 2];
            afrag[i][1] = *(const uint32_t*)&As[buf][r + 8][tq * 2];
        }

        #pragma unroll
        for (int i = 0; i < 4; i++)
            #pragma unroll
            for (int j = 0; j < 4; j++)
                mma_f16(c[i][j], afrag[i], bfrag[j]);
    }

    // epilogue -> fp16 batch-major (fully coalesced half2 stream per row)
    #pragma unroll
    for (int i = 0; i < 4; i++) {
        const int row0 = by * GBM + wm + i * 16 + grp;
        if (row0 < MTOT) {   // grp<8 and MTOT%16==0 => row0+8 also in range
            #pragma unroll
            for (int j = 0; j < 4; j++) {
                const int col = bx * GBN + wn + j * 8 + tq * 2;
                __half2 h01 = __floats2half2_rn(c[i][j][0], c[i][j][1]);
                __half2 h23 = __floats2half2_rn(c[i][j][2], c[i][j][3]);
                *(__half2*)(g_support_h + (size_t)row0 * DOUT + col)       = h01;
                *(__half2*)(g_support_h + (size_t)(row0 + 8) * DOUT + col) = h23;
            }
        }
    }
}

// ---------------- SpMM: one warp per (row, batch), fp16 gather, f32 accum ----------------
__device__ __forceinline__ uint4 ldg_cg_v4(const void* p) {
    uint4 r;
    asm volatile("ld.global.cg.v4.u32 {%0,%1,%2,%3}, [%4];"
                 : "=r"(r.x), "=r"(r.y), "=r"(r.z), "=r"(r.w) : "l"(p));
    return r;
}

__device__ __forceinline__ void fma_half8(float* acc, uint4 x, float v) {
    float2 f0 = __half22float2(*(__half2*)&x.x);
    float2 f1 = __half22float2(*(__half2*)&x.y);
    float2 f2 = __half22float2(*(__half2*)&x.z);
    float2 f3 = __half22float2(*(__half2*)&x.w);
    acc[0] = fmaf(v, f0.x, acc[0]); acc[1] = fmaf(v, f0.y, acc[1]);
    acc[2] = fmaf(v, f1.x, acc[2]); acc[3] = fmaf(v, f1.y, acc[3]);
    acc[4] = fmaf(v, f2.x, acc[4]); acc[5] = fmaf(v, f2.y, acc[5]);
    acc[6] = fmaf(v, f3.x, acc[6]); acc[7] = fmaf(v, f3.y, acc[7]);
}

__global__ __launch_bounds__(256)
void spmm_kernel(const float* __restrict__ bias, float* __restrict__ out) {
    const int warp = threadIdx.x >> 5;
    const int lane = threadIdx.x & 31;
    const int row  = blockIdx.x * 8 + warp;   // 6250 * 8 == 50000 exactly
    const int b    = blockIdx.y;

    const int s = g_rowptr[row];
    const int e = g_rowptr[row + 1];
    const __half* sup = g_support_h + (size_t)b * NN * DOUT;

    float acc[8];
    #pragma unroll
    for (int q = 0; q < 8; q++) acc[q] = 0.f;

    int i = s;
    // unroll-by-4: 4 outstanding LDG.128 gathers per lane (L2-only via .cg)
    for (; i + 3 < e; i += 4) {
        int2 ev[4];
        uint4 x[4];
        #pragma unroll
        for (int u = 0; u < 4; u++) ev[u] = g_csr[i + u];
        #pragma unroll
        for (int u = 0; u < 4; u++)
            x[u] = ldg_cg_v4((const uint4*)(sup + (size_t)ev[u].x * DOUT) + lane);
        #pragma unroll
        for (int u = 0; u < 4; u++)
            fma_half8(acc, x[u], __int_as_float(ev[u].y));
    }
    for (; i < e; i++) {
        int2 ev = g_csr[i];
        uint4 x = ldg_cg_v4((const uint4*)(sup + (size_t)ev.x * DOUT) + lane);
        fma_half8(acc, x, __int_as_float(ev.y));
    }

    const float4* b4 = (const float4*)(bias + lane * 8);
    float4 bb0 = b4[0], bb1 = b4[1];
    float4 o0 = make_float4(acc[0] + bb0.x, acc[1] + bb0.y, acc[2] + bb0.z, acc[3] + bb0.w);
    float4 o1 = make_float4(acc[4] + bb1.x, acc[5] + bb1.y, acc[6] + bb1.z, acc[7] + bb1.w);

    float* o = out + ((size_t)b * NN + row) * DOUT + lane * 8;
    *(float4*)(o)     = o0;
    *(float4*)(o + 4) = o1;
}

// ---------------- launch ----------------
extern "C" void kernel_launch(void* const* d_in, const int* in_sizes, int n_in,
                              void* d_out, int out_size) {
    const float* X    = (const float*)d_in[0];   // [4, 50000, 256]
    const int*   rows = (const int*)  d_in[1];   // [1.6M]
    const int*   cols = (const int*)  d_in[2];   // [1.6M]
    const float* vals = (const float*)d_in[3];   // [1.6M]
    const float* W    = (const float*)d_in[4];   // [256, 256]
    const float* bias = (const float*)d_in[5];   // [256]
    float* out = (float*)d_out;

    const int nScanBlk = (NN + SCAN_B - 1) / SCAN_B;   // 98 (<=148 SMs: lookback safe)

    // CSR build (4 kernels, single-pass scan)
    zero_kernel<<<(NN + 255) / 256, 256>>>();
    hist_kernel<<<(NE + 255) / 256, 256>>>(rows);
    scan_onepass_kernel<<<nScanBlk, SCAN_B>>>();
    scatter_kernel<<<(NE + 255) / 256, 256>>>(rows, cols, vals);

    // Dense projection on fp16 tensor cores, fp16 batch-major output
    dim3 ggrid(DOUT / GBN, (MTOT + GBM - 1) / GBM);   // (2, 1563)
    gemm_tc_kernel<<<ggrid, 256>>>(X, W);

    // SpMM + bias: warp per (row, batch) — 200K warps for latency hiding
    dim3 sgrid(NN / 8, NB);                           // (6250, 4)
    spmm_kernel<<<sgrid, 256>>>(bias, out);
}

// round 13
// speedup vs baseline: 1.1666x; 1.0045x over previous
#include <cuda_runtime.h>
#include <cuda_fp16.h>
#include <cstdint>

// Problem constants (match reference setup_inputs)
#define NN     50000          // nodes
#define NE     1600000        // edges
#define DIN    256
#define DOUT   256
#define NB     4              // batch
#define MTOT   (NB * NN)      // 200000 rows for the flattened GEMM

// ---------------- device scratch (no allocations allowed) ----------------
// Support stored batch-major: [batch][node][DOUT] fp16
__device__ __half  g_support_h[(size_t)NB * NN * DOUT];  // 102.4 MB
__device__ int     g_deg[NN];
__device__ unsigned long long g_state[128];   // decoupled-lookback {flag,agg}
__device__ int     g_rowptr[NN + 1];
__device__ int     g_wptr[NN];
__device__ int2    g_csr[NE];          // {col, val-as-int} packed per edge

// ---------------- CSR build ----------------
__global__ void zero_kernel() {
    int j = blockIdx.x * blockDim.x + threadIdx.x;
    if (j < NN) g_deg[j] = 0;
    if (j < 128) g_state[j] = 0ULL;
}

__global__ void hist_kernel(const int* __restrict__ rows) {
    int e = blockIdx.x * blockDim.x + threadIdx.x;
    if (e < NE) atomicAdd(&g_deg[rows[e]], 1);
}

// Single-pass exclusive scan with decoupled lookback (98 blocks <= 148 SMs)
#define SCAN_B 512
__global__ void scan_onepass_kernel() {
    __shared__ int sh[SCAN_B];
    __shared__ unsigned s_prefix;
    const int tid = threadIdx.x;
    const int blk = blockIdx.x;
    const int j = blk * SCAN_B + tid;

    int v = (j < NN) ? g_deg[j] : 0;
    sh[tid] = v;
    __syncthreads();
    #pragma unroll
    for (int off = 1; off < SCAN_B; off <<= 1) {
        int t = (tid >= off) ? sh[tid - off] : 0;
        __syncthreads();
        sh[tid] += t;
        __syncthreads();
    }

    // publish block aggregate (flag=1 packed in high word)
    if (tid == SCAN_B - 1)
        atomicExch(&g_state[blk], (1ULL << 32) | (unsigned)sh[SCAN_B - 1]);

    // warp 0: sum aggregates of all predecessor blocks (warp-parallel lookback)
    if (tid < 32) {
        unsigned sum = 0;
        for (int base = blk - 1; base >= 0; base -= 32) {
            int p = base - tid;
            if (p >= 0) {
                unsigned long long st;
                do { st = atomicAdd(&g_state[p], 0ULL); } while ((st >> 32) == 0ULL);
                sum += (unsigned)st;
            }
        }
        sum = __reduce_add_sync(0xffffffffu, sum);
        if (tid == 0) s_prefix = sum;
    }
    __syncthreads();

    if (j < NN) {
        int rp = (int)s_prefix + sh[tid] - v;   // exclusive prefix
        g_rowptr[j] = rp;
        g_wptr[j]   = rp;
    }
    if (blk == 0 && tid == 0) g_rowptr[NN] = NE;
}

__global__ void scatter_kernel(const int* __restrict__ rows,
                               const int* __restrict__ cols,
                               const float* __restrict__ vals) {
    int e = blockIdx.x * blockDim.x + threadIdx.x;
    if (e < NE) {
        int r = rows[e];
        int p = atomicAdd(&g_wptr[r], 1);
        g_csr[p] = make_int2(cols[e], __float_as_int(vals[e]));
    }
}

// ---------------- GEMM: support = X @ W via fp16 tensor cores ----------------
// Block tile 128x256 (full DOUT width), 512 threads / 16 warps (2m x 8n),
// warp tile 64x32, BK=16, double-buffered fp16 smem, mma.m16n8k8.f32.f16.f16.f32.
#define GBM 128
#define GBN 256
#define GBK 16
#define BSTR 264   // Bs row stride in halfs: 132 words, tq-step lands +8 banks

__device__ __forceinline__ void mma_f16(float* c, const uint32_t* a, uint32_t b) {
    asm volatile(
        "mma.sync.aligned.m16n8k8.row.col.f32.f16.f16.f32 "
        "{%0,%1,%2,%3}, {%4,%5}, {%6}, {%0,%1,%2,%3};"
        : "+f"(c[0]), "+f"(c[1]), "+f"(c[2]), "+f"(c[3])
        : "r"(a[0]), "r"(a[1]), "r"(b));
}

__device__ __forceinline__ uint2 f4_to_h4(float4 v) {
    __half2 lo = __floats2half2_rn(v.x, v.y);
    __half2 hi = __floats2half2_rn(v.z, v.w);
    return make_uint2(*(uint32_t*)&lo, *(uint32_t*)&hi);
}

__global__ __launch_bounds__(512, 1)
void gemm_tc_kernel(const float* __restrict__ A, const float* __restrict__ W) {
    // A: row-major, k contiguous (natural half2 fragment loads)
    __shared__ __half As[2][GBM][GBK];     // 8 KB
    __shared__ __half Bs[2][GBK][BSTR];    // 16.5 KB (padded)

    const int by  = blockIdx.x;            // 0..1562
    const int tid = threadIdx.x;
    const int warp = tid >> 5;
    const int lane = tid & 31;
    const int wm = (warp & 1) * 64;        // warp m offset in tile
    const int wn = (warp >> 1) * 32;       // warp n offset: 0..224
    const int grp = lane >> 2;             // 0..7
    const int tq  = lane & 3;              // 0..3

    // A tile: 128 rows x 16 k f32 = 512 float4 -> 1 per thread
    const int aRow = tid >> 2;             // 0..127
    const int aK4  = (tid & 3) * 4;        // 0,4,8,12
    // B tile: 16 k x 256 n f32 = 1024 float4 -> 2 per thread
    const int bK   = tid >> 5;             // 0..15
    const int bC   = lane * 4;             // 0..124 (second half at +128)

    const int gRow = by * GBM + aRow;
    const bool aOk = (gRow < MTOT);
    const float* aPtr = A + (size_t)(aOk ? gRow : 0) * DIN;
    const float* wPtr = W + (size_t)bK * DOUT;

    float c[4][4][4];
    #pragma unroll
    for (int i = 0; i < 4; i++)
        #pragma unroll
        for (int j = 0; j < 4; j++)
            #pragma unroll
            for (int r = 0; r < 4; r++) c[i][j][r] = 0.f;

    // prefetch chunk 0
    float4 av = make_float4(0.f, 0.f, 0.f, 0.f);
    if (aOk) av = *(const float4*)(aPtr + aK4);
    float4 bv0 = *(const float4*)(wPtr + bC);
    float4 bv1 = *(const float4*)(wPtr + bC + 128);

    const int NCHUNK = DIN / GBK;   // 16
    for (int chunk = 0; chunk < NCHUNK; chunk++) {
        const int buf = chunk & 1;

        *(uint2*)&As[buf][aRow][aK4]     = f4_to_h4(av);
        *(uint2*)&Bs[buf][bK][bC]        = f4_to_h4(bv0);
        *(uint2*)&Bs[buf][bK][bC + 128]  = f4_to_h4(bv1);
        __syncthreads();

        if (chunk + 1 < NCHUNK) {
            const int kn = (chunk + 1) * GBK;
            if (aOk) av = *(const float4*)(aPtr + kn + aK4);
            bv0 = *(const float4*)(wPtr + (size_t)kn * DOUT + bC);
            bv1 = *(const float4*)(wPtr + (size_t)kn * DOUT + bC + 128);
        }

        #pragma unroll
        for (int ks = 0; ks < 2; ks++) {
            const int kb = ks * 8;

            // B fragments: b = half2(B[kb+2tq][col], B[kb+2tq+1][col])
            uint32_t bfrag[4];
            #pragma unroll
            for (int j = 0; j < 4; j++) {
                const int col = wn + j * 8 + grp;
                __half blo = Bs[buf][kb + tq * 2][col];
                __half bhi = Bs[buf][kb + tq * 2 + 1][col];
                __half2 bb = __halves2half2(blo, bhi);
                bfrag[j] = *(uint32_t*)&bb;
            }

            // A fragments: natural half2 loads (k contiguous)
            uint32_t afrag[4][2];
            #pragma unroll
            for (int i = 0; i < 4; i++) {
                const int r = wm + i * 16 + grp;
                afrag[i][0] = *(const uint32_t*)&As[buf][r][kb + tq * 2];
                afrag[i][1] = *(const uint32_t*)&As[buf][r + 8][kb + tq * 2];
            }

            #pragma unroll
            for (int i = 0; i < 4; i++)
                #pragma unroll
                for (int j = 0; j < 4; j++)
                    mma_f16(c[i][j], afrag[i], bfrag[j]);
        }
    }

    // epilogue -> fp16 batch-major
    #pragma unroll
    for (int i = 0; i < 4; i++) {
        const int row0 = by * GBM + wm + i * 16 + grp;
        if (row0 < MTOT) {   // 16-row subtiles aligned; MTOT%16==0 => row0+8 ok
            #pragma unroll
            for (int j = 0; j < 4; j++) {
                const int col = wn + j * 8 + tq * 2;
                __half2 h01 = __floats2half2_rn(c[i][j][0], c[i][j][1]);
                __half2 h23 = __floats2half2_rn(c[i][j][2], c[i][j][3]);
                *(__half2*)(g_support_h + (size_t)row0 * DOUT + col)       = h01;
                *(__half2*)(g_support_h + (size_t)(row0 + 8) * DOUT + col) = h23;
            }
        }
    }
}

// ---------------- SpMM: one warp per (row, batch), fp16 gather, f32 accum ----------------
__device__ __forceinline__ uint4 ldg_cg_v4(const void* p) {
    uint4 r;
    asm volatile("ld.global.cg.v4.u32 {%0,%1,%2,%3}, [%4];"
                 : "=r"(r.x), "=r"(r.y), "=r"(r.z), "=r"(r.w) : "l"(p));
    return r;
}

__device__ __forceinline__ void fma_half8(float* acc, uint4 x, float v) {
    float2 f0 = __half22float2(*(__half2*)&x.x);
    float2 f1 = __half22float2(*(__half2*)&x.y);
    float2 f2 = __half22float2(*(__half2*)&x.z);
    float2 f3 = __half22float2(*(__half2*)&x.w);
    acc[0] = fmaf(v, f0.x, acc[0]); acc[1] = fmaf(v, f0.y, acc[1]);
    acc[2] = fmaf(v, f1.x, acc[2]); acc[3] = fmaf(v, f1.y, acc[3]);
    acc[4] = fmaf(v, f2.x, acc[4]); acc[5] = fmaf(v, f2.y, acc[5]);
    acc[6] = fmaf(v, f3.x, acc[6]); acc[7] = fmaf(v, f3.y, acc[7]);
}

__global__ __launch_bounds__(256)
void spmm_kernel(const float* __restrict__ bias, float* __restrict__ out) {
    const int warp = threadIdx.x >> 5;
    const int lane = threadIdx.x & 31;
    const int row  = blockIdx.x * 8 + warp;   // 6250 * 8 == 50000 exactly
    const int b    = blockIdx.y;

    const int s = g_rowptr[row];
    const int e = g_rowptr[row + 1];
    const __half* sup = g_support_h + (size_t)b * NN * DOUT;

    float acc[8];
    #pragma unroll
    for (int q = 0; q < 8; q++) acc[q] = 0.f;

    int i = s;
    // unroll-by-4: 4 outstanding LDG.128 gathers per lane (L2-only via .cg)
    for (; i + 3 < e; i += 4) {
        int2 ev[4];
        uint4 x[4];
        #pragma unroll
        for (int u = 0; u < 4; u++) ev[u] = g_csr[i + u];
        #pragma unroll
        for (int u = 0; u < 4; u++)
            x[u] = ldg_cg_v4((const uint4*)(sup + (size_t)ev[u].x * DOUT) + lane);
        #pragma unroll
        for (int u = 0; u < 4; u++)
            fma_half8(acc, x[u], __int_as_float(ev[u].y));
    }
    for (; i < e; i++) {
        int2 ev = g_csr[i];
        uint4 x = ldg_cg_v4((const uint4*)(sup + (size_t)ev.x * DOUT) + lane);
        fma_half8(acc, x, __int_as_float(ev.y));
    }

    const float4* b4 = (const float4*)(bias + lane * 8);
    float4 bb0 = b4[0], bb1 = b4[1];
    float4 o0 = make_float4(acc[0] + bb0.x, acc[1] + bb0.y, acc[2] + bb0.z, acc[3] + bb0.w);
    float4 o1 = make_float4(acc[4] + bb1.x, acc[5] + bb1.y, acc[6] + bb1.z, acc[7] + bb1.w);

    float* o = out + ((size_t)b * NN + row) * DOUT + lane * 8;
    *(float4*)(o)     = o0;
    *(float4*)(o + 4) = o1;
}

// ---------------- launch ----------------
extern "C" void kernel_launch(void* const* d_in, const int* in_sizes, int n_in,
                              void* d_out, int out_size) {
    const float* X    = (const float*)d_in[0];   // [4, 50000, 256]
    const int*   rows = (const int*)  d_in[1];   // [1.6M]
    const int*   cols = (const int*)  d_in[2];   // [1.6M]
    const float* vals = (const float*)d_in[3];   // [1.6M]
    const float* W    = (const float*)d_in[4];   // [256, 256]
    const float* bias = (const float*)d_in[5];   // [256]
    float* out = (float*)d_out;

    const int nScanBlk = (NN + SCAN_B - 1) / SCAN_B;   // 98 (<=148 SMs: lookback safe)

    // Order: zero, hist, scan, GEMM, scatter, spmm.
    // (gemm is independent of scan/scatter; placing it 4th puts it in the
    //  ncu profiled slot so next round finally sees GEMM pipe data.)
    zero_kernel<<<(NN + 255) / 256, 256>>>();
    hist_kernel<<<(NE + 255) / 256, 256>>>(rows);
    scan_onepass_kernel<<<nScanBlk, SCAN_B>>>();

    gemm_tc_kernel<<<(MTOT + GBM - 1) / GBM, 512>>>(X, W);   // 1563 blocks

    scatter_kernel<<<(NE + 255) / 256, 256>>>(rows, cols, vals);

    // SpMM + bias: warp per (row, batch) — 200K warps for latency hiding
    dim3 sgrid(NN / 8, NB);                           // (6250, 4)
    spmm_kernel<<<sgrid, 256>>>(bias, out);
}

// round 17
// speedup vs baseline: 1.2093x; 1.0366x over previous
#include <cuda_runtime.h>
#include <cuda_fp16.h>
#include <cstdint>

// Problem constants (match reference setup_inputs)
#define NN     50000          // nodes
#define NE     1600000        // edges
#define DIN    256
#define DOUT   256
#define NB     4              // batch
#define MTOT   (NB * NN)      // 200000 rows for the flattened GEMM

// ---------------- device scratch (no allocations allowed) ----------------
// Support stored batch-major: [batch][node][DOUT] fp16
__device__ __half  g_support_h[(size_t)NB * NN * DOUT];  // 102.4 MB
__device__ int     g_deg[NN];
__device__ unsigned long long g_state[128];   // decoupled-lookback {flag,agg}
__device__ int     g_rowptr[NN + 1];
__device__ int     g_wptr[NN];
__device__ int2    g_csr[NE];          // {col, val-as-int} packed per edge

// ---------------- CSR build ----------------
__global__ void zero_kernel() {
    int j = blockIdx.x * blockDim.x + threadIdx.x;
    if (j < NN) g_deg[j] = 0;
    if (j < 128) g_state[j] = 0ULL;
}

__global__ void hist_kernel(const int* __restrict__ rows) {
    int e = blockIdx.x * blockDim.x + threadIdx.x;
    if (e < NE) atomicAdd(&g_deg[rows[e]], 1);
}

// Single-pass exclusive scan with decoupled lookback (98 blocks <= 148 SMs)
#define SCAN_B 512
__global__ void scan_onepass_kernel() {
    __shared__ int sh[SCAN_B];
    __shared__ unsigned s_prefix;
    const int tid = threadIdx.x;
    const int blk = blockIdx.x;
    const int j = blk * SCAN_B + tid;

    int v = (j < NN) ? g_deg[j] : 0;
    sh[tid] = v;
    __syncthreads();
    #pragma unroll
    for (int off = 1; off < SCAN_B; off <<= 1) {
        int t = (tid >= off) ? sh[tid - off] : 0;
        __syncthreads();
        sh[tid] += t;
        __syncthreads();
    }

    // publish block aggregate (flag=1 packed in high word)
    if (tid == SCAN_B - 1)
        atomicExch(&g_state[blk], (1ULL << 32) | (unsigned)sh[SCAN_B - 1]);

    // warp 0: sum aggregates of all predecessor blocks (warp-parallel lookback)
    if (tid < 32) {
        unsigned sum = 0;
        for (int base = blk - 1; base >= 0; base -= 32) {
            int p = base - tid;
            if (p >= 0) {
                unsigned long long st;
                do { st = atomicAdd(&g_state[p], 0ULL); } while ((st >> 32) == 0ULL);
                sum += (unsigned)st;
            }
        }
        sum = __reduce_add_sync(0xffffffffu, sum);
        if (tid == 0) s_prefix = sum;
    }
    __syncthreads();

    if (j < NN) {
        int rp = (int)s_prefix + sh[tid] - v;   // exclusive prefix
        g_rowptr[j] = rp;
        g_wptr[j]   = rp;
    }
    if (blk == 0 && tid == 0) g_rowptr[NN] = NE;
}

__global__ void scatter_kernel(const int* __restrict__ rows,
                               const int* __restrict__ cols,
                               const float* __restrict__ vals) {
    int e = blockIdx.x * blockDim.x + threadIdx.x;
    if (e < NE) {
        int r = rows[e];
        int p = atomicAdd(&g_wptr[r], 1);
        g_csr[p] = make_int2(cols[e], __float_as_int(vals[e]));
    }
}

// ---------------- GEMM: support = X @ W via fp16 tensor cores ----------------
// Block tile 128x256 (full DOUT width), 512 threads / 16 warps (2m x 8n),
// warp tile 64x32, BK=16, double-buffered fp16 smem.
// mma.sync.m16n8k16: one instruction per former k8-pair (half the issue count).
#define GBM 128
#define GBN 256
#define GBK 16
#define BSTR 264   // Bs row stride in halfs: 132 words, tq-step lands +8 banks

__device__ __forceinline__ void mma_f16_k16(float* c, const uint32_t* a, const uint32_t* b) {
    asm volatile(
        "mma.sync.aligned.m16n8k16.row.col.f32.f16.f16.f32 "
        "{%0,%1,%2,%3}, {%4,%5,%6,%7}, {%8,%9}, {%0,%1,%2,%3};"
        : "+f"(c[0]), "+f"(c[1]), "+f"(c[2]), "+f"(c[3])
        : "r"(a[0]), "r"(a[1]), "r"(a[2]), "r"(a[3]), "r"(b[0]), "r"(b[1]));
}

__device__ __forceinline__ uint2 f4_to_h4(float4 v) {
    __half2 lo = __floats2half2_rn(v.x, v.y);
    __half2 hi = __floats2half2_rn(v.z, v.w);
    return make_uint2(*(uint32_t*)&lo, *(uint32_t*)&hi);
}

__global__ __launch_bounds__(512, 1)
void gemm_tc_kernel(const float* __restrict__ A, const float* __restrict__ W) {
    // A: row-major, k contiguous (natural half2 fragment loads)
    __shared__ __half As[2][GBM][GBK];     // 8 KB
    __shared__ __half Bs[2][GBK][BSTR];    // 16.5 KB (padded)

    const int by  = blockIdx.x;            // 0..1562
    const int tid = threadIdx.x;
    const int warp = tid >> 5;
    const int lane = tid & 31;
    const int wm = (warp & 1) * 64;        // warp m offset in tile
    const int wn = (warp >> 1) * 32;       // warp n offset: 0..224
    const int grp = lane >> 2;             // 0..7
    const int tq  = lane & 3;              // 0..3

    // A tile: 128 rows x 16 k f32 = 512 float4 -> 1 per thread
    const int aRow = tid >> 2;             // 0..127
    const int aK4  = (tid & 3) * 4;        // 0,4,8,12
    // B tile: 16 k x 256 n f32 = 1024 float4 -> 2 per thread
    const int bK   = tid >> 5;             // 0..15
    const int bC   = lane * 4;             // 0..124 (second half at +128)

    const int gRow = by * GBM + aRow;
    const bool aOk = (gRow < MTOT);
    const float* aPtr = A + (size_t)(aOk ? gRow : 0) * DIN;
    const float* wPtr = W + (size_t)bK * DOUT;

    float c[4][4][4];
    #pragma unroll
    for (int i = 0; i < 4; i++)
        #pragma unroll
        for (int j = 0; j < 4; j++)
            #pragma unroll
            for (int r = 0; r < 4; r++) c[i][j][r] = 0.f;

    // prefetch chunk 0
    float4 av = make_float4(0.f, 0.f, 0.f, 0.f);
    if (aOk) av = *(const float4*)(aPtr + aK4);
    float4 bv0 = *(const float4*)(wPtr + bC);
    float4 bv1 = *(const float4*)(wPtr + bC + 128);

    const int NCHUNK = DIN / GBK;   // 16
    for (int chunk = 0; chunk < NCHUNK; chunk++) {
        const int buf = chunk & 1;

        *(uint2*)&As[buf][aRow][aK4]     = f4_to_h4(av);
        *(uint2*)&Bs[buf][bK][bC]        = f4_to_h4(bv0);
        *(uint2*)&Bs[buf][bK][bC + 128]  = f4_to_h4(bv1);
        __syncthreads();

        if (chunk + 1 < NCHUNK) {
            const int kn = (chunk + 1) * GBK;
            if (aOk) av = *(const float4*)(aPtr + kn + aK4);
            bv0 = *(const float4*)(wPtr + (size_t)kn * DOUT + bC);
            bv1 = *(const float4*)(wPtr + (size_t)kn * DOUT + bC + 128);
        }

        // B fragments (k16): b0 = k[2tq..2tq+1], b1 = k[8+2tq..8+2tq+1]
        uint32_t bfrag[4][2];
        #pragma unroll
        for (int j = 0; j < 4; j++) {
            const int col = wn + j * 8 + grp;
            __half2 b0 = __halves2half2(Bs[buf][tq * 2][col],
                                        Bs[buf][tq * 2 + 1][col]);
            __half2 b1 = __halves2half2(Bs[buf][8 + tq * 2][col],
                                        Bs[buf][8 + tq * 2 + 1][col]);
            bfrag[j][0] = *(uint32_t*)&b0;
            bfrag[j][1] = *(uint32_t*)&b1;
        }

        // A fragments (k16): a0=(r,k0-7) a1=(r+8,k0-7) a2=(r,k8-15) a3=(r+8,k8-15)
        uint32_t afrag[4][4];
        #pragma unroll
        for (int i = 0; i < 4; i++) {
            const int r = wm + i * 16 + grp;
            afrag[i][0] = *(const uint32_t*)&As[buf][r][tq * 2];
            afrag[i][1] = *(const uint32_t*)&As[buf][r + 8][tq * 2];
            afrag[i][2] = *(const uint32_t*)&As[buf][r][8 + tq * 2];
            afrag[i][3] = *(const uint32_t*)&As[buf][r + 8][8 + tq * 2];
        }

        #pragma unroll
        for (int i = 0; i < 4; i++)
            #pragma unroll
            for (int j = 0; j < 4; j++)
                mma_f16_k16(c[i][j], afrag[i], bfrag[j]);
    }

    // epilogue -> fp16 batch-major
    #pragma unroll
    for (int i = 0; i < 4; i++) {
        const int row0 = by * GBM + wm + i * 16 + grp;
        if (row0 < MTOT) {   // 16-row subtiles aligned; MTOT%16==0 => row0+8 ok
            #pragma unroll
            for (int j = 0; j < 4; j++) {
                const int col = wn + j * 8 + tq * 2;
                __half2 h01 = __floats2half2_rn(c[i][j][0], c[i][j][1]);
                __half2 h23 = __floats2half2_rn(c[i][j][2], c[i][j][3]);
                *(__half2*)(g_support_h + (size_t)row0 * DOUT + col)       = h01;
                *(__half2*)(g_support_h + (size_t)(row0 + 8) * DOUT + col) = h23;
            }
        }
    }
}

// ---------------- SpMM: one warp per (row, batch), fp16 gather, f32 accum ----------------
__device__ __forceinline__ uint4 ldg_cg_v4(const void* p) {
    uint4 r;
    asm volatile("ld.global.cg.v4.u32 {%0,%1,%2,%3}, [%4];"
                 : "=r"(r.x), "=r"(r.y), "=r"(r.z), "=r"(r.w) : "l"(p));
    return r;
}

__device__ __forceinline__ void fma_half8(float* acc, uint4 x, float v) {
    float2 f0 = __half22float2(*(__half2*)&x.x);
    float2 f1 = __half22float2(*(__half2*)&x.y);
    float2 f2 = __half22float2(*(__half2*)&x.z);
    float2 f3 = __half22float2(*(__half2*)&x.w);
    acc[0] = fmaf(v, f0.x, acc[0]); acc[1] = fmaf(v, f0.y, acc[1]);
    acc[2] = fmaf(v, f1.x, acc[2]); acc[3] = fmaf(v, f1.y, acc[3]);
    acc[4] = fmaf(v, f2.x, acc[4]); acc[5] = fmaf(v, f2.y, acc[5]);
    acc[6] = fmaf(v, f3.x, acc[6]); acc[7] = fmaf(v, f3.y, acc[7]);
}

__global__ __launch_bounds__(256)
void spmm_kernel(const float* __restrict__ bias, float* __restrict__ out) {
    const int warp = threadIdx.x >> 5;
    const int lane = threadIdx.x & 31;
    const int row  = blockIdx.x * 8 + warp;   // 6250 * 8 == 50000 exactly
    const int b    = blockIdx.y;

    const int s = g_rowptr[row];
    const int e = g_rowptr[row + 1];
    const __half* sup = g_support_h + (size_t)b * NN * DOUT;

    float acc[8];
    #pragma unroll
    for (int q = 0; q < 8; q++) acc[q] = 0.f;

    int i = s;
    // unroll-by-4: 4 outstanding LDG.128 gathers per lane (L2-only via .cg)
    for (; i + 3 < e; i += 4) {
        int2 ev[4];
        uint4 x[4];
        #pragma unroll
        for (int u = 0; u < 4; u++) ev[u] = g_csr[i + u];
        #pragma unroll
        for (int u = 0; u < 4; u++)
            x[u] = ldg_cg_v4((const uint4*)(sup + (size_t)ev[u].x * DOUT) + lane);
        #pragma unroll
        for (int u = 0; u < 4; u++)
            fma_half8(acc, x[u], __int_as_float(ev[u].y));
    }
    for (; i < e; i++) {
        int2 ev = g_csr[i];
        uint4 x = ldg_cg_v4((const uint4*)(sup + (size_t)ev.x * DOUT) + lane);
        fma_half8(acc, x, __int_as_float(ev.y));
    }

    const float4* b4 = (const float4*)(bias + lane * 8);
    float4 bb0 = b4[0], bb1 = b4[1];
    float4 o0 = make_float4(acc[0] + bb0.x, acc[1] + bb0.y, acc[2] + bb0.z, acc[3] + bb0.w);
    float4 o1 = make_float4(acc[4] + bb1.x, acc[5] + bb1.y, acc[6] + bb1.z, acc[7] + bb1.w);

    float* o = out + ((size_t)b * NN + row) * DOUT + lane * 8;
    *(float4*)(o)     = o0;
    *(float4*)(o + 4) = o1;
}

// ---------------- launch ----------------
extern "C" void kernel_launch(void* const* d_in, const int* in_sizes, int n_in,
                              void* d_out, int out_size) {
    const float* X    = (const float*)d_in[0];   // [4, 50000, 256]
    const int*   rows = (const int*)  d_in[1];   // [1.6M]
    const int*   cols = (const int*)  d_in[2];   // [1.6M]
    const float* vals = (const float*)d_in[3];   // [1.6M]
    const float* W    = (const float*)d_in[4];   // [256, 256]
    const float* bias = (const float*)d_in[5];   // [256]
    float* out = (float*)d_out;

    const int nScanBlk = (NN + SCAN_B - 1) / SCAN_B;   // 98 (<=148 SMs: lookback safe)

    // Order keeps GEMM in the ncu-profiled slot.
    zero_kernel<<<(NN + 255) / 256, 256>>>();
    hist_kernel<<<(NE + 255) / 256, 256>>>(rows);
    scan_onepass_kernel<<<nScanBlk, SCAN_B>>>();

    gemm_tc_kernel<<<(MTOT + GBM - 1) / GBM, 512>>>(X, W);   // 1563 blocks

    scatter_kernel<<<(NE + 255) / 256, 256>>>(rows, cols, vals);

    // SpMM + bias: warp per (row, batch) — 200K warps for latency hiding
    dim3 sgrid(NN / 8, NB);                           // (6250, 4)
    spmm_kernel<<<sgrid, 256>>>(bias, out);
}